// round 6
// baseline (speedup 1.0000x reference)
#include <cuda_runtime.h>
#include <cstdint>

#define Bn 16384
#define Fn 512
#define Pn 128
#define NTOT (Bn * Pn)            // 2,097,152
#define NTOT2 (2 * NTOT)          // 4,194,304 (src+tgt combined)
#define NBLK_DELTA (NTOT / 256)   // 8192

// ---------------- static device scratch (no runtime allocation) ----------------
__device__ __align__(128) float g_P[Fn * Pn];    // normalized projections [f][p]
__device__ __align__(128) float g_PT[Pn * Fn];   // transposed             [p][f]
__device__ __align__(128) float g_inv[Pn];       // per-column 1/||col||
__device__ __align__(128) unsigned int g_projU[NTOT2];   // flipped proj [t][p][b]
__device__ __align__(128) float g_sortedVal[NTOT2];      // sorted values [t][p][j]
__device__ __align__(128) unsigned short g_srcIdx[NTOT]; // src payload b [p][j]
__device__ __align__(128) float g_delta[Bn * Pn];        // [b][p]
__device__ float g_partials[NBLK_DELTA];

// ---------------- helpers ----------------
__device__ __forceinline__ unsigned int fflip(float f) {
    unsigned int u = __float_as_uint(f);
    return u ^ ((u >> 31) ? 0xFFFFFFFFu : 0x80000000u);
}
__device__ __forceinline__ float funflip(unsigned int u) {
    return __uint_as_float(u ^ ((u >> 31) ? 0x80000000u : 0xFFFFFFFFu));
}

// packed fp32x2 FMA: two IEEE fp32 FMAs per instruction, bitwise == 2x fmaf
__device__ __forceinline__ void fma2(unsigned long long& d,
                                     unsigned long long a,
                                     unsigned long long b) {
    asm("fma.rn.f32x2 %0, %1, %2, %0;" : "+l"(d) : "l"(a), "l"(b));
}
__device__ __forceinline__ unsigned long long dup2(float f) {
    unsigned long long r;
    unsigned u = __float_as_uint(f);
    asm("mov.b64 %0, {%1, %1};" : "=l"(r) : "r"(u));
    return r;
}
__device__ __forceinline__ float2 unpk(unsigned long long v) {
    unsigned lo, hi;
    asm("mov.b64 {%0, %1}, %2;" : "=r"(lo), "=r"(hi) : "l"(v));
    return make_float2(__uint_as_float(lo), __uint_as_float(hi));
}

// ---------------- kernel A1: column sums -> g_inv (bitwise-stable order) ---
__global__ void col_inv_kernel(const float* __restrict__ projs) {
    __shared__ float sm[32][128];
    const int tid = threadIdx.x;
    float s = 0.f;
    for (int f0 = 0; f0 < Fn; f0 += 32) {
#pragma unroll
        for (int it = 0; it < 8; ++it) {
            int f4 = it * 128 + tid;
            int r = f4 >> 5, c4 = (f4 & 31) * 4;
            float4 v = *(const float4*)&projs[(size_t)(f0 + r) * Pn + c4];
            sm[r][c4 + 0] = v.x;
            sm[r][c4 + 1] = v.y;
            sm[r][c4 + 2] = v.z;
            sm[r][c4 + 3] = v.w;
        }
        __syncthreads();
#pragma unroll
        for (int fl = 0; fl < 32; ++fl) {
            float v = sm[fl][tid];
            s += v * v;
        }
        __syncthreads();
    }
    g_inv[tid] = 1.0f / sqrtf(s);
}

// ---------------- kernel A2: scale + write g_P and g_PT --------------------
__global__ void scale_write_kernel(const float* __restrict__ projs) {
    __shared__ float tp[128][33];
    const int f0 = blockIdx.x * 32;
    const int tid = threadIdx.x;
#pragma unroll
    for (int it = 0; it < 4; ++it) {
        int f4 = it * 256 + tid;
        int r = f4 >> 5, c4 = (f4 & 31) * 4;
        float4 v = *(const float4*)&projs[(size_t)(f0 + r) * Pn + c4];
        float4 w;
        w.x = v.x * g_inv[c4 + 0];
        w.y = v.y * g_inv[c4 + 1];
        w.z = v.z * g_inv[c4 + 2];
        w.w = v.w * g_inv[c4 + 3];
        *(float4*)&g_P[(size_t)(f0 + r) * Pn + c4] = w;
        tp[c4 + 0][r] = w.x;
        tp[c4 + 1][r] = w.y;
        tp[c4 + 2][r] = w.z;
        tp[c4 + 3][r] = w.w;
    }
    __syncthreads();
    const int p = tid >> 1;
    const int fl0 = (tid & 1) * 16;
#pragma unroll
    for (int i = 0; i < 16; ++i)
        g_PT[(size_t)p * Fn + f0 + fl0 + i] = tp[p][fl0 + i];
}

// ---------------- kernel B: projection GEMM (f32x2), writes flipped u32 ----
__global__ __launch_bounds__(256, 2) void proj_gemm_kernel(
    const float* __restrict__ src, const float* __restrict__ tgt) {
    extern __shared__ float sm[];
    float* As = sm;                  // [16][132] transposed: [k][b]
    float* Bs = sm + 16 * 132;       // [16][132] : [k][p]
    float* Ts = sm + 2 * 16 * 132;   // [128][129]: [p][b]

    const int t = blockIdx.y;
    const float* A = t ? tgt : src;
    const int b0 = blockIdx.x * 128;
    const int tid = threadIdx.x;
    const int ty = tid >> 4;
    const int tx = tid & 15;

    unsigned long long acc2[4][8];
#pragma unroll
    for (int q = 0; q < 4; ++q)
#pragma unroll
        for (int j = 0; j < 8; ++j) acc2[q][j] = 0ull;

    for (int k0 = 0; k0 < Fn; k0 += 16) {
#pragma unroll
        for (int it = 0; it < 2; ++it) {
            int idx = tid + it * 256;
            int r = idx >> 2, c4 = (idx & 3) * 4;
            float4 v = *(const float4*)&A[(size_t)(b0 + r) * Fn + k0 + c4];
            As[(c4 + 0) * 132 + r] = v.x;
            As[(c4 + 1) * 132 + r] = v.y;
            As[(c4 + 2) * 132 + r] = v.z;
            As[(c4 + 3) * 132 + r] = v.w;
        }
#pragma unroll
        for (int it = 0; it < 2; ++it) {
            int idx = tid + it * 256;
            int r = idx >> 5, c4 = (idx & 31) * 4;
            *(float4*)&Bs[r * 132 + c4] = *(const float4*)&g_P[(k0 + r) * Pn + c4];
        }
        __syncthreads();
#pragma unroll
        for (int k = 0; k < 16; ++k) {
            ulonglong2 aL = *(ulonglong2*)&As[k * 132 + ty * 4];
            ulonglong2 aH = *(ulonglong2*)&As[k * 132 + 64 + ty * 4];
            float4 bv0 = *(float4*)&Bs[k * 132 + tx * 4];
            float4 bv1 = *(float4*)&Bs[k * 132 + 64 + tx * 4];
            unsigned long long a2[4] = {aL.x, aL.y, aH.x, aH.y};
            unsigned long long b2[8];
            b2[0] = dup2(bv0.x); b2[1] = dup2(bv0.y);
            b2[2] = dup2(bv0.z); b2[3] = dup2(bv0.w);
            b2[4] = dup2(bv1.x); b2[5] = dup2(bv1.y);
            b2[6] = dup2(bv1.z); b2[7] = dup2(bv1.w);
#pragma unroll
            for (int q = 0; q < 4; ++q)
#pragma unroll
                for (int j = 0; j < 8; ++j)
                    fma2(acc2[q][j], a2[q], b2[j]);
        }
        __syncthreads();
    }

#pragma unroll
    for (int q = 0; q < 4; ++q) {
#pragma unroll
        for (int j = 0; j < 8; ++j) {
            float2 v = unpk(acc2[q][j]);
            int i0 = 2 * q, i1 = 2 * q + 1;
            int r0 = (i0 < 4) ? (ty * 4 + i0) : (64 + ty * 4 + (i0 - 4));
            int r1 = (i1 < 4) ? (ty * 4 + i1) : (64 + ty * 4 + (i1 - 4));
            int c = (j < 4) ? (tx * 4 + j) : (64 + tx * 4 + (j - 4));
            Ts[c * 129 + r0] = v.x;
            Ts[c * 129 + r1] = v.y;
        }
    }
    __syncthreads();

    const int p = tid >> 1;
    const int half = (tid & 1) * 64;
    unsigned int* dst = g_projU + (size_t)(t * Pn + p) * Bn + b0 + half;
    const float* srcrow = Ts + p * 129 + half;
#pragma unroll 4
    for (int i = 0; i < 64; ++i) dst[i] = fflip(srcrow[i]);
}

// ---------------- kernel C: custom segmented radix sort (4x8-bit, stable) --
// 256 blocks: s<128 -> src segment (pairs: payload=b); s>=128 -> tgt (keys).
// Elements warp-striped (i = w*512 + j*32 + lane) so per-warp match-based
// ranking in (warp, slot, lane) order == array-position order -> stable.
#define SIT 16   // items per thread (16384 / 1024)
__global__ __launch_bounds__(1024, 1) void seg_sort_kernel() {
    extern __shared__ unsigned int sh[];
    unsigned int* keyBuf = sh;                                   // 16384 u32
    unsigned short* valBuf = (unsigned short*)(keyBuf + Bn);     // 16384 u16
    unsigned int* hist = (unsigned int*)(valBuf + Bn);           // 8192 u32
    __shared__ unsigned int wtot[32];

    const int s = blockIdx.x;
    const int t = s >> 7;            // 0 = src (pairs), 1 = tgt (keys only)
    const int p = s & 127;
    const bool pairs = (t == 0);
    const int tid = threadIdx.x;
    const int lane = tid & 31;
    const int w = tid >> 5;

    const unsigned int* segIn = g_projU + ((size_t)s << 14);
    unsigned int k[SIT];
    unsigned short v[SIT];
#pragma unroll
    for (int j = 0; j < SIT; ++j) {
        int i = (w << 9) + (j << 5) + lane;
        k[j] = segIn[i];
        v[j] = (unsigned short)i;
    }

#pragma unroll
    for (int pass = 0; pass < 4; ++pass) {
        const int sh_amt = pass * 8;
        // zero per-warp histograms: hist[d*32 + w]
#pragma unroll
        for (int z = 0; z < 8; ++z) hist[tid + z * 1024] = 0;
        __syncthreads();

        // histogram (per-warp counters, match-based leader update)
#pragma unroll
        for (int j = 0; j < SIT; ++j) {
            unsigned d = (k[j] >> sh_amt) & 255u;
            unsigned mask = __match_any_sync(0xFFFFFFFFu, d);
            int leader = __ffs(mask) - 1;
            if (lane == leader) hist[d * 32 + w] += __popc(mask);
        }
        __syncthreads();

        // exclusive scan of hist[0..8191] flattened (d-major, then warp)
        {
            int base = tid * 8;
            unsigned c[8], sum = 0;
#pragma unroll
            for (int z = 0; z < 8; ++z) {
                c[z] = hist[base + z];
                unsigned tmp = sum;
                sum += c[z];
                c[z] = tmp;
            }
            unsigned incl = sum;
#pragma unroll
            for (int o = 1; o < 32; o <<= 1) {
                unsigned n = __shfl_up_sync(0xFFFFFFFFu, incl, o);
                if (lane >= o) incl += n;
            }
            unsigned laneExcl = incl - sum;
            if (lane == 31) wtot[w] = incl;
            __syncthreads();
            if (w == 0) {
                unsigned x = wtot[lane];
                unsigned inc = x;
#pragma unroll
                for (int o = 1; o < 32; o <<= 1) {
                    unsigned n = __shfl_up_sync(0xFFFFFFFFu, inc, o);
                    if (lane >= o) inc += n;
                }
                wtot[lane] = inc - x;
            }
            __syncthreads();
            unsigned offs = wtot[w] + laneExcl;
#pragma unroll
            for (int z = 0; z < 8; ++z) hist[base + z] = offs + c[z];
        }
        __syncthreads();

        // scatter (stable: rank = scanned offset + running count + lane prefix)
#pragma unroll
        for (int j = 0; j < SIT; ++j) {
            unsigned d = (k[j] >> sh_amt) & 255u;
            unsigned mask = __match_any_sync(0xFFFFFFFFu, d);
            int leader = __ffs(mask) - 1;
            unsigned prefix = __popc(mask & ((1u << lane) - 1u));
            unsigned cnt = 0;
            if (lane == leader) {
                cnt = hist[d * 32 + w];
                hist[d * 32 + w] = cnt + __popc(mask);
            }
            cnt = __shfl_sync(0xFFFFFFFFu, cnt, leader);
            unsigned pos = cnt + prefix;
            keyBuf[pos] = k[j];
            if (pairs) valBuf[pos] = v[j];
        }
        __syncthreads();

        // reload warp-striped for next pass / output
#pragma unroll
        for (int j = 0; j < SIT; ++j) {
            int i = (w << 9) + (j << 5) + lane;
            k[j] = keyBuf[i];
            if (pairs) v[j] = valBuf[i];
        }
        __syncthreads();
    }

    // write sorted output (coalesced)
    float* outV = g_sortedVal + ((size_t)s << 14);
    unsigned short* outI = g_srcIdx + ((size_t)p << 14);
#pragma unroll
    for (int j = 0; j < SIT; ++j) {
        int i = (w << 9) + (j << 5) + lane;
        outV[i] = funflip(k[j]);
        if (pairs) outI[i] = v[j];
    }
}
static constexpr size_t SORT_SMEM = (size_t)Bn * 4 + (size_t)Bn * 2 + 8192 * 4; // 128KB

// ---------------- kernel D: delta + scatter + dist partials ----------------
__global__ void delta_kernel() {
    int j = blockIdx.x * 256 + threadIdx.x;
    int p = j >> 14;
    float sv = g_sortedVal[j];                       // src half (t=0)
    float tv = g_sortedVal[j + NTOT];                // tgt half (t=1)
    int b = (int)g_srcIdx[j];
    float d = tv - sv;
    g_delta[(size_t)b * Pn + p] = d;

    float s = d * d;
#pragma unroll
    for (int o = 16; o; o >>= 1) s += __shfl_xor_sync(0xFFFFFFFFu, s, o);
    __shared__ float ws[8];
    int lane = threadIdx.x & 31, wid = threadIdx.x >> 5;
    if (lane == 0) ws[wid] = s;
    __syncthreads();
    if (threadIdx.x == 0) {
        float tt = 0.f;
#pragma unroll
        for (int x = 0; x < 8; ++x) tt += ws[x];
        g_partials[blockIdx.x] = tt;
    }
}

// ---------------- kernel E: movement GEMM (f32x2) fused with row-normalize --
__global__ __launch_bounds__(256, 2) void mv_norm_kernel(float* __restrict__ out) {
    extern __shared__ float sm[];
    float* As   = sm;                    // [32][36]
    float* Bs   = sm + 32 * 36;          // [32][516]
    float* part = Bs + 32 * 516;         // [32][65]
    float* inv  = part + 32 * 65;        // [32]

    const int b0 = blockIdx.x * 32;
    const int tid = threadIdx.x;
    const int ty = tid >> 6;
    const int tx = tid & 63;

    unsigned long long acc2[4][8];
#pragma unroll
    for (int q = 0; q < 4; ++q)
#pragma unroll
        for (int j = 0; j < 8; ++j) acc2[q][j] = 0ull;

    for (int k0 = 0; k0 < Pn; k0 += 32) {
        {
            int r = tid >> 3, c4 = (tid & 7) * 4;
            float4 v = *(const float4*)&g_delta[(size_t)(b0 + r) * Pn + k0 + c4];
            As[(c4 + 0) * 36 + r] = v.x;
            As[(c4 + 1) * 36 + r] = v.y;
            As[(c4 + 2) * 36 + r] = v.z;
            As[(c4 + 3) * 36 + r] = v.w;
        }
#pragma unroll
        for (int it = 0; it < 16; ++it) {
            int idx = tid + it * 256;
            int r = idx >> 7, c4 = (idx & 127) * 4;
            *(float4*)&Bs[r * 516 + c4] = *(const float4*)&g_PT[(size_t)(k0 + r) * Fn + c4];
        }
        __syncthreads();
#pragma unroll
        for (int k = 0; k < 32; ++k) {
            ulonglong2 aL = *(ulonglong2*)&As[k * 36 + ty * 4];
            ulonglong2 aH = *(ulonglong2*)&As[k * 36 + 16 + ty * 4];
            float4 bv0 = *(float4*)&Bs[k * 516 + tx * 4];
            float4 bv1 = *(float4*)&Bs[k * 516 + 256 + tx * 4];
            unsigned long long a2[4] = {aL.x, aL.y, aH.x, aH.y};
            unsigned long long b2[8];
            b2[0] = dup2(bv0.x); b2[1] = dup2(bv0.y);
            b2[2] = dup2(bv0.z); b2[3] = dup2(bv0.w);
            b2[4] = dup2(bv1.x); b2[5] = dup2(bv1.y);
            b2[6] = dup2(bv1.z); b2[7] = dup2(bv1.w);
#pragma unroll
            for (int q = 0; q < 4; ++q)
#pragma unroll
                for (int j = 0; j < 8; ++j)
                    fma2(acc2[q][j], a2[q], b2[j]);
        }
        __syncthreads();
    }

    float acc[8][8];
#pragma unroll
    for (int q = 0; q < 4; ++q)
#pragma unroll
        for (int j = 0; j < 8; ++j) {
            float2 v = unpk(acc2[q][j]);
            acc[2 * q][j] = v.x;
            acc[2 * q + 1][j] = v.y;
        }

#pragma unroll
    for (int i = 0; i < 8; ++i) {
        int r = (i < 4) ? (ty * 4 + i) : (16 + ty * 4 + (i - 4));
        float s = 0.f;
#pragma unroll
        for (int j = 0; j < 8; ++j) s += acc[i][j] * acc[i][j];
        part[r * 65 + tx] = s;
    }
    __syncthreads();
    if (tid < 32) {
        float s = 0.f;
        for (int x = 0; x < 64; ++x) s += part[tid * 65 + x];
        inv[tid] = 1.0f / sqrtf(s);
    }
    __syncthreads();

#pragma unroll
    for (int i = 0; i < 8; ++i) {
        int r = (i < 4) ? (ty * 4 + i) : (16 + ty * 4 + (i - 4));
        float iv = inv[r];
        size_t row = (size_t)(b0 + r) * Fn;
#pragma unroll
        for (int j = 0; j < 4; ++j)
            out[row + tx * 4 + j] = acc[i][j] * iv;
#pragma unroll
        for (int j = 0; j < 4; ++j)
            out[row + 256 + tx * 4 + j] = acc[i][4 + j] * iv;
    }
}

// ---------------- kernel G: deterministic dist reduction -------------------
__global__ void dist_kernel(float* __restrict__ out) {
    __shared__ float sm[1024];
    int tid = threadIdx.x;
    float s = 0.f;
    for (int j = tid; j < NBLK_DELTA; j += 1024) s += g_partials[j];
    sm[tid] = s;
    __syncthreads();
    for (int st = 512; st; st >>= 1) {
        if (tid < st) sm[tid] += sm[tid + st];
        __syncthreads();
    }
    if (tid == 0) out[0] = sm[0] * (1.0f / (float)NTOT);
}

// ---------------- launch ----------------
extern "C" void kernel_launch(void* const* d_in, const int* in_sizes, int n_in,
                              void* d_out, int out_size) {
    const float* src   = (const float*)d_in[0];
    const float* tgt   = (const float*)d_in[1];
    const float* projs = (const float*)d_in[2];
    float* out = (float*)d_out;

    const int smem_proj = (2 * 16 * 132 + 128 * 129) * 4;          // 82,944 B
    const int smem_mv   = (32 * 36 + 32 * 516 + 32 * 65 + 32) * 4; // 79,104 B
    cudaFuncSetAttribute(proj_gemm_kernel,
                         cudaFuncAttributeMaxDynamicSharedMemorySize, smem_proj);
    cudaFuncSetAttribute(mv_norm_kernel,
                         cudaFuncAttributeMaxDynamicSharedMemorySize, smem_mv);
    cudaFuncSetAttribute(seg_sort_kernel,
                         cudaFuncAttributeMaxDynamicSharedMemorySize, (int)SORT_SMEM);

    col_inv_kernel<<<1, 128>>>(projs);                  // #1
    scale_write_kernel<<<Fn / 32, 256>>>(projs);        // #2

    dim3 gb(Bn / 128, 2);
    proj_gemm_kernel<<<gb, 256, smem_proj>>>(src, tgt); // #3

    seg_sort_kernel<<<256, 1024, SORT_SMEM>>>();        // #4  <- ncu window

    delta_kernel<<<NBLK_DELTA, 256>>>();                // #5

    bool has_dist = (out_size != Bn * Fn);   // B*F+1 (or 1) -> dist present
    float* mv_out = has_dist ? out + 1 : out;

    if (has_dist) {
        dist_kernel<<<1, 1024>>>(out);       // 1 block; overlaps with mv wave
    }
    if (out_size >= Bn * Fn) {
        mv_norm_kernel<<<Bn / 32, 256, smem_mv>>>(mv_out);
    }
}

// round 7
// speedup vs baseline: 1.1182x; 1.1182x over previous
#include <cuda_runtime.h>
#include <cstdint>

#define Bn 16384
#define Fn 512
#define Pn 128
#define NTOT (Bn * Pn)            // 2,097,152
#define NTOT2 (2 * NTOT)          // 4,194,304 (src+tgt combined)
#define NBLK_DELTA (NTOT / 256)   // 8192

// ---------------- static device scratch (no runtime allocation) ----------------
__device__ __align__(128) float g_P[Fn * Pn];    // normalized projections [f][p]
__device__ __align__(128) float g_PT[Pn * Fn];   // transposed             [p][f]
__device__ __align__(128) float g_inv[Pn];       // per-column 1/||col||
__device__ __align__(128) unsigned int g_projU[NTOT2];   // flipped proj [t][p][b]
__device__ __align__(128) float g_sortedVal[NTOT2];      // sorted values [t][p][j]
__device__ __align__(128) unsigned short g_srcIdx[NTOT]; // src payload b [p][j]
__device__ __align__(128) float g_delta[Bn * Pn];        // [b][p]
__device__ float g_partials[NBLK_DELTA];

// ---------------- helpers ----------------
__device__ __forceinline__ unsigned int fflip(float f) {
    unsigned int u = __float_as_uint(f);
    return u ^ ((u >> 31) ? 0xFFFFFFFFu : 0x80000000u);
}
__device__ __forceinline__ float funflip(unsigned int u) {
    return __uint_as_float(u ^ ((u >> 31) ? 0x80000000u : 0xFFFFFFFFu));
}

// packed fp32x2 FMA: two IEEE fp32 FMAs per instruction, bitwise == 2x fmaf
__device__ __forceinline__ void fma2(unsigned long long& d,
                                     unsigned long long a,
                                     unsigned long long b) {
    asm("fma.rn.f32x2 %0, %1, %2, %0;" : "+l"(d) : "l"(a), "l"(b));
}
__device__ __forceinline__ unsigned long long dup2(float f) {
    unsigned long long r;
    unsigned u = __float_as_uint(f);
    asm("mov.b64 %0, {%1, %1};" : "=l"(r) : "r"(u));
    return r;
}
__device__ __forceinline__ float2 unpk(unsigned long long v) {
    unsigned lo, hi;
    asm("mov.b64 {%0, %1}, %2;" : "=r"(lo), "=r"(hi) : "l"(v));
    return make_float2(__uint_as_float(lo), __uint_as_float(hi));
}

// ---------------- kernel A1: column sums -> g_inv (bitwise-stable order) ---
__global__ void col_inv_kernel(const float* __restrict__ projs) {
    __shared__ float sm[32][128];
    const int tid = threadIdx.x;
    float s = 0.f;
    for (int f0 = 0; f0 < Fn; f0 += 32) {
#pragma unroll
        for (int it = 0; it < 8; ++it) {
            int f4 = it * 128 + tid;
            int r = f4 >> 5, c4 = (f4 & 31) * 4;
            float4 v = *(const float4*)&projs[(size_t)(f0 + r) * Pn + c4];
            sm[r][c4 + 0] = v.x;
            sm[r][c4 + 1] = v.y;
            sm[r][c4 + 2] = v.z;
            sm[r][c4 + 3] = v.w;
        }
        __syncthreads();
#pragma unroll
        for (int fl = 0; fl < 32; ++fl) {
            float v = sm[fl][tid];
            s += v * v;
        }
        __syncthreads();
    }
    g_inv[tid] = 1.0f / sqrtf(s);
}

// ---------------- kernel A2: scale + write g_P and g_PT --------------------
__global__ void scale_write_kernel(const float* __restrict__ projs) {
    __shared__ float tp[128][33];
    const int f0 = blockIdx.x * 32;
    const int tid = threadIdx.x;
#pragma unroll
    for (int it = 0; it < 4; ++it) {
        int f4 = it * 256 + tid;
        int r = f4 >> 5, c4 = (f4 & 31) * 4;
        float4 v = *(const float4*)&projs[(size_t)(f0 + r) * Pn + c4];
        float4 w;
        w.x = v.x * g_inv[c4 + 0];
        w.y = v.y * g_inv[c4 + 1];
        w.z = v.z * g_inv[c4 + 2];
        w.w = v.w * g_inv[c4 + 3];
        *(float4*)&g_P[(size_t)(f0 + r) * Pn + c4] = w;
        tp[c4 + 0][r] = w.x;
        tp[c4 + 1][r] = w.y;
        tp[c4 + 2][r] = w.z;
        tp[c4 + 3][r] = w.w;
    }
    __syncthreads();
    const int p = tid >> 1;
    const int fl0 = (tid & 1) * 16;
#pragma unroll
    for (int i = 0; i < 16; ++i)
        g_PT[(size_t)p * Fn + f0 + fl0 + i] = tp[p][fl0 + i];
}

// ---------------- kernel B: projection GEMM (f32x2), writes flipped u32 ----
__global__ __launch_bounds__(256, 2) void proj_gemm_kernel(
    const float* __restrict__ src, const float* __restrict__ tgt) {
    extern __shared__ float sm[];
    float* As = sm;                  // [16][132] transposed: [k][b]
    float* Bs = sm + 16 * 132;       // [16][132] : [k][p]
    float* Ts = sm + 2 * 16 * 132;   // [128][129]: [p][b]

    const int t = blockIdx.y;
    const float* A = t ? tgt : src;
    const int b0 = blockIdx.x * 128;
    const int tid = threadIdx.x;
    const int ty = tid >> 4;
    const int tx = tid & 15;

    unsigned long long acc2[4][8];
#pragma unroll
    for (int q = 0; q < 4; ++q)
#pragma unroll
        for (int j = 0; j < 8; ++j) acc2[q][j] = 0ull;

    for (int k0 = 0; k0 < Fn; k0 += 16) {
#pragma unroll
        for (int it = 0; it < 2; ++it) {
            int idx = tid + it * 256;
            int r = idx >> 2, c4 = (idx & 3) * 4;
            float4 v = *(const float4*)&A[(size_t)(b0 + r) * Fn + k0 + c4];
            As[(c4 + 0) * 132 + r] = v.x;
            As[(c4 + 1) * 132 + r] = v.y;
            As[(c4 + 2) * 132 + r] = v.z;
            As[(c4 + 3) * 132 + r] = v.w;
        }
#pragma unroll
        for (int it = 0; it < 2; ++it) {
            int idx = tid + it * 256;
            int r = idx >> 5, c4 = (idx & 31) * 4;
            *(float4*)&Bs[r * 132 + c4] = *(const float4*)&g_P[(k0 + r) * Pn + c4];
        }
        __syncthreads();
#pragma unroll
        for (int k = 0; k < 16; ++k) {
            ulonglong2 aL = *(ulonglong2*)&As[k * 132 + ty * 4];
            ulonglong2 aH = *(ulonglong2*)&As[k * 132 + 64 + ty * 4];
            float4 bv0 = *(float4*)&Bs[k * 132 + tx * 4];
            float4 bv1 = *(float4*)&Bs[k * 132 + 64 + tx * 4];
            unsigned long long a2[4] = {aL.x, aL.y, aH.x, aH.y};
            unsigned long long b2[8];
            b2[0] = dup2(bv0.x); b2[1] = dup2(bv0.y);
            b2[2] = dup2(bv0.z); b2[3] = dup2(bv0.w);
            b2[4] = dup2(bv1.x); b2[5] = dup2(bv1.y);
            b2[6] = dup2(bv1.z); b2[7] = dup2(bv1.w);
#pragma unroll
            for (int q = 0; q < 4; ++q)
#pragma unroll
                for (int j = 0; j < 8; ++j)
                    fma2(acc2[q][j], a2[q], b2[j]);
        }
        __syncthreads();
    }

#pragma unroll
    for (int q = 0; q < 4; ++q) {
#pragma unroll
        for (int j = 0; j < 8; ++j) {
            float2 v = unpk(acc2[q][j]);
            int i0 = 2 * q, i1 = 2 * q + 1;
            int r0 = (i0 < 4) ? (ty * 4 + i0) : (64 + ty * 4 + (i0 - 4));
            int r1 = (i1 < 4) ? (ty * 4 + i1) : (64 + ty * 4 + (i1 - 4));
            int c = (j < 4) ? (tx * 4 + j) : (64 + tx * 4 + (j - 4));
            Ts[c * 129 + r0] = v.x;
            Ts[c * 129 + r1] = v.y;
        }
    }
    __syncthreads();

    const int p = tid >> 1;
    const int half = (tid & 1) * 64;
    unsigned int* dst = g_projU + (size_t)(t * Pn + p) * Bn + b0 + half;
    const float* srcrow = Ts + p * 129 + half;
#pragma unroll 4
    for (int i = 0; i < 64; ++i) dst[i] = fflip(srcrow[i]);
}

// ---------------- kernel C: custom segmented radix sort (4x8-bit, stable) --
// 256 blocks: s<128 -> src segment (pairs: payload=b); s>=128 -> tgt (keys).
// Warp w owns contiguous indices [512w, 512w+512), processed (j, lane)
// ascending -> per-warp match ranking is stable.
// Histogram layout hist[w*256 + d]: leader accesses within a warp hit banks
// d%32 (distinct d -> ~conflict-free) instead of the single bank w that the
// d*32+w layout produced (the 32-way replay chain ncu flagged in round 6).
// Scan traverses in digit-major (d, w) order via transposed addressing.
#define SIT 16   // items per thread (16384 / 1024)
__global__ __launch_bounds__(1024, 1) void seg_sort_kernel() {
    extern __shared__ unsigned int sh[];
    unsigned int* keyBuf = sh;                                   // 16384 u32
    unsigned short* valBuf = (unsigned short*)(keyBuf + Bn);     // 16384 u16
    unsigned int* hist = (unsigned int*)(valBuf + Bn);           // 8192 u32
    __shared__ unsigned int wtot[32];

    const int s = blockIdx.x;
    const int t = s >> 7;            // 0 = src (pairs), 1 = tgt (keys only)
    const int p = s & 127;
    const bool pairs = (t == 0);
    const int tid = threadIdx.x;
    const int lane = tid & 31;
    const int w = tid >> 5;

    const unsigned int* segIn = g_projU + ((size_t)s << 14);
    unsigned int k[SIT];
    unsigned short v[SIT];
#pragma unroll
    for (int j = 0; j < SIT; ++j) {
        int i = (w << 9) + (j << 5) + lane;
        k[j] = segIn[i];
        v[j] = (unsigned short)i;
    }

#pragma unroll
    for (int pass = 0; pass < 4; ++pass) {
        const int sh_amt = pass * 8;
        // zero histograms (tid + z*1024: conflict-free)
#pragma unroll
        for (int z = 0; z < 8; ++z) hist[tid + z * 1024] = 0;
        __syncthreads();

        // histogram: per-warp counters at hist[w*256 + d]
#pragma unroll
        for (int j = 0; j < SIT; ++j) {
            unsigned d = (k[j] >> sh_amt) & 255u;
            unsigned mask = __match_any_sync(0xFFFFFFFFu, d);
            int leader = __ffs(mask) - 1;
            if (lane == leader) hist[(w << 8) + d] += __popc(mask);
        }
        __syncthreads();

        // exclusive scan in digit-major (d, w) flat order over transposed
        // storage: fi = d*32 + w_; thread tid covers fi in [8*tid, 8*tid+8)
        // -> d = tid>>2 (constant per thread), w_ = (tid&3)*8 + z.
        {
            const int d = tid >> 2;
            const int wbase = (tid & 3) * 8;
            unsigned c[8], sum = 0;
#pragma unroll
            for (int z = 0; z < 8; ++z) {
                c[z] = hist[((wbase + z) << 8) + d];
                unsigned tmp = sum;
                sum += c[z];
                c[z] = tmp;
            }
            unsigned incl = sum;
#pragma unroll
            for (int o = 1; o < 32; o <<= 1) {
                unsigned n = __shfl_up_sync(0xFFFFFFFFu, incl, o);
                if (lane >= o) incl += n;
            }
            unsigned laneExcl = incl - sum;
            if (lane == 31) wtot[w] = incl;
            __syncthreads();
            if (w == 0) {
                unsigned x = wtot[lane];
                unsigned inc = x;
#pragma unroll
                for (int o = 1; o < 32; o <<= 1) {
                    unsigned n = __shfl_up_sync(0xFFFFFFFFu, inc, o);
                    if (lane >= o) inc += n;
                }
                wtot[lane] = inc - x;
            }
            __syncthreads();
            unsigned offs = wtot[w] + laneExcl;
#pragma unroll
            for (int z = 0; z < 8; ++z)
                hist[((wbase + z) << 8) + d] = offs + c[z];
        }
        __syncthreads();

        // scatter (stable: rank = scanned offset + running count + lane prefix)
#pragma unroll
        for (int j = 0; j < SIT; ++j) {
            unsigned d = (k[j] >> sh_amt) & 255u;
            unsigned mask = __match_any_sync(0xFFFFFFFFu, d);
            int leader = __ffs(mask) - 1;
            unsigned prefix = __popc(mask & ((1u << lane) - 1u));
            unsigned cnt = 0;
            if (lane == leader) {
                cnt = hist[(w << 8) + d];
                hist[(w << 8) + d] = cnt + __popc(mask);
            }
            cnt = __shfl_sync(0xFFFFFFFFu, cnt, leader);
            unsigned pos = cnt + prefix;
            keyBuf[pos] = k[j];
            if (pairs) valBuf[pos] = v[j];
        }
        __syncthreads();

        // reload (lane-consecutive: conflict-free)
#pragma unroll
        for (int j = 0; j < SIT; ++j) {
            int i = (w << 9) + (j << 5) + lane;
            k[j] = keyBuf[i];
            if (pairs) v[j] = valBuf[i];
        }
        __syncthreads();
    }

    // write sorted output (coalesced)
    float* outV = g_sortedVal + ((size_t)s << 14);
    unsigned short* outI = g_srcIdx + ((size_t)p << 14);
#pragma unroll
    for (int j = 0; j < SIT; ++j) {
        int i = (w << 9) + (j << 5) + lane;
        outV[i] = funflip(k[j]);
        if (pairs) outI[i] = v[j];
    }
}
static constexpr size_t SORT_SMEM = (size_t)Bn * 4 + (size_t)Bn * 2 + 8192 * 4; // 128KB

// ---------------- kernel D: delta + scatter + dist partials ----------------
__global__ void delta_kernel() {
    int j = blockIdx.x * 256 + threadIdx.x;
    int p = j >> 14;
    float sv = g_sortedVal[j];                       // src half (t=0)
    float tv = g_sortedVal[j + NTOT];                // tgt half (t=1)
    int b = (int)g_srcIdx[j];
    float d = tv - sv;
    g_delta[(size_t)b * Pn + p] = d;

    float s = d * d;
#pragma unroll
    for (int o = 16; o; o >>= 1) s += __shfl_xor_sync(0xFFFFFFFFu, s, o);
    __shared__ float ws[8];
    int lane = threadIdx.x & 31, wid = threadIdx.x >> 5;
    if (lane == 0) ws[wid] = s;
    __syncthreads();
    if (threadIdx.x == 0) {
        float tt = 0.f;
#pragma unroll
        for (int x = 0; x < 8; ++x) tt += ws[x];
        g_partials[blockIdx.x] = tt;
    }
}

// ---------------- kernel E: movement GEMM (f32x2) fused with row-normalize --
__global__ __launch_bounds__(256, 2) void mv_norm_kernel(float* __restrict__ out) {
    extern __shared__ float sm[];
    float* As   = sm;                    // [32][36]
    float* Bs   = sm + 32 * 36;          // [32][516]
    float* part = Bs + 32 * 516;         // [32][65]
    float* inv  = part + 32 * 65;        // [32]

    const int b0 = blockIdx.x * 32;
    const int tid = threadIdx.x;
    const int ty = tid >> 6;
    const int tx = tid & 63;

    unsigned long long acc2[4][8];
#pragma unroll
    for (int q = 0; q < 4; ++q)
#pragma unroll
        for (int j = 0; j < 8; ++j) acc2[q][j] = 0ull;

    for (int k0 = 0; k0 < Pn; k0 += 32) {
        {
            int r = tid >> 3, c4 = (tid & 7) * 4;
            float4 v = *(const float4*)&g_delta[(size_t)(b0 + r) * Pn + k0 + c4];
            As[(c4 + 0) * 36 + r] = v.x;
            As[(c4 + 1) * 36 + r] = v.y;
            As[(c4 + 2) * 36 + r] = v.z;
            As[(c4 + 3) * 36 + r] = v.w;
        }
#pragma unroll
        for (int it = 0; it < 16; ++it) {
            int idx = tid + it * 256;
            int r = idx >> 7, c4 = (idx & 127) * 4;
            *(float4*)&Bs[r * 516 + c4] = *(const float4*)&g_PT[(size_t)(k0 + r) * Fn + c4];
        }
        __syncthreads();
#pragma unroll
        for (int k = 0; k < 32; ++k) {
            ulonglong2 aL = *(ulonglong2*)&As[k * 36 + ty * 4];
            ulonglong2 aH = *(ulonglong2*)&As[k * 36 + 16 + ty * 4];
            float4 bv0 = *(float4*)&Bs[k * 516 + tx * 4];
            float4 bv1 = *(float4*)&Bs[k * 516 + 256 + tx * 4];
            unsigned long long a2[4] = {aL.x, aL.y, aH.x, aH.y};
            unsigned long long b2[8];
            b2[0] = dup2(bv0.x); b2[1] = dup2(bv0.y);
            b2[2] = dup2(bv0.z); b2[3] = dup2(bv0.w);
            b2[4] = dup2(bv1.x); b2[5] = dup2(bv1.y);
            b2[6] = dup2(bv1.z); b2[7] = dup2(bv1.w);
#pragma unroll
            for (int q = 0; q < 4; ++q)
#pragma unroll
                for (int j = 0; j < 8; ++j)
                    fma2(acc2[q][j], a2[q], b2[j]);
        }
        __syncthreads();
    }

    float acc[8][8];
#pragma unroll
    for (int q = 0; q < 4; ++q)
#pragma unroll
        for (int j = 0; j < 8; ++j) {
            float2 v = unpk(acc2[q][j]);
            acc[2 * q][j] = v.x;
            acc[2 * q + 1][j] = v.y;
        }

#pragma unroll
    for (int i = 0; i < 8; ++i) {
        int r = (i < 4) ? (ty * 4 + i) : (16 + ty * 4 + (i - 4));
        float s = 0.f;
#pragma unroll
        for (int j = 0; j < 8; ++j) s += acc[i][j] * acc[i][j];
        part[r * 65 + tx] = s;
    }
    __syncthreads();
    if (tid < 32) {
        float s = 0.f;
        for (int x = 0; x < 64; ++x) s += part[tid * 65 + x];
        inv[tid] = 1.0f / sqrtf(s);
    }
    __syncthreads();

#pragma unroll
    for (int i = 0; i < 8; ++i) {
        int r = (i < 4) ? (ty * 4 + i) : (16 + ty * 4 + (i - 4));
        float iv = inv[r];
        size_t row = (size_t)(b0 + r) * Fn;
#pragma unroll
        for (int j = 0; j < 4; ++j)
            out[row + tx * 4 + j] = acc[i][j] * iv;
#pragma unroll
        for (int j = 0; j < 4; ++j)
            out[row + 256 + tx * 4 + j] = acc[i][4 + j] * iv;
    }
}

// ---------------- kernel G: deterministic dist reduction -------------------
__global__ void dist_kernel(float* __restrict__ out) {
    __shared__ float sm[1024];
    int tid = threadIdx.x;
    float s = 0.f;
    for (int j = tid; j < NBLK_DELTA; j += 1024) s += g_partials[j];
    sm[tid] = s;
    __syncthreads();
    for (int st = 512; st; st >>= 1) {
        if (tid < st) sm[tid] += sm[tid + st];
        __syncthreads();
    }
    if (tid == 0) out[0] = sm[0] * (1.0f / (float)NTOT);
}

// ---------------- launch ----------------
extern "C" void kernel_launch(void* const* d_in, const int* in_sizes, int n_in,
                              void* d_out, int out_size) {
    const float* src   = (const float*)d_in[0];
    const float* tgt   = (const float*)d_in[1];
    const float* projs = (const float*)d_in[2];
    float* out = (float*)d_out;

    const int smem_proj = (2 * 16 * 132 + 128 * 129) * 4;          // 82,944 B
    const int smem_mv   = (32 * 36 + 32 * 516 + 32 * 65 + 32) * 4; // 79,104 B
    cudaFuncSetAttribute(proj_gemm_kernel,
                         cudaFuncAttributeMaxDynamicSharedMemorySize, smem_proj);
    cudaFuncSetAttribute(mv_norm_kernel,
                         cudaFuncAttributeMaxDynamicSharedMemorySize, smem_mv);
    cudaFuncSetAttribute(seg_sort_kernel,
                         cudaFuncAttributeMaxDynamicSharedMemorySize, (int)SORT_SMEM);

    col_inv_kernel<<<1, 128>>>(projs);                  // #1
    scale_write_kernel<<<Fn / 32, 256>>>(projs);        // #2

    dim3 gb(Bn / 128, 2);
    proj_gemm_kernel<<<gb, 256, smem_proj>>>(src, tgt); // #3

    seg_sort_kernel<<<256, 1024, SORT_SMEM>>>();        // #4  <- ncu window

    delta_kernel<<<NBLK_DELTA, 256>>>();                // #5

    bool has_dist = (out_size != Bn * Fn);   // B*F+1 (or 1) -> dist present
    float* mv_out = has_dist ? out + 1 : out;

    if (has_dist) {
        dist_kernel<<<1, 1024>>>(out);       // 1 block; overlaps with mv wave
    }
    if (out_size >= Bn * Fn) {
        mv_norm_kernel<<<Bn / 32, 256, smem_mv>>>(mv_out);
    }
}